// round 1
// baseline (speedup 1.0000x reference)
#include <cuda_runtime.h>
#include <math.h>

// ---------------- problem constants ----------------
#define HOPSZ 551
#define MAXH  2048      // H = N/551 + 1 = 1903 for N = 1<<20
#define LCH   128       // samples per chunk (one chunk per thread)
#define WARM  352       // warmup samples: 256 (LPC transient) + 96 (biquad) margin
#define TPB   64        // chunks (threads) per block

// scratch (device globals; no allocation allowed)
__device__ float g_cb[MAXH * 5];
__device__ float g_cd[MAXH * 5];
__device__ float g_p[MAXH];

// ---------------- kernel 1: per-hop coefficients ----------------
// LFO -> MLP waveshaper -> allpass pole p -> normalized cb/cd rows.
__global__ void coef_kernel(
    const float* __restrict__ g2,
    const float* __restrict__ depth, const float* __restrict__ bias,
    const float* __restrict__ lfo_omega, const float* __restrict__ lfo_phi,
    const float* __restrict__ lfo_r_logit,
    const float* __restrict__ W_in, const float* __restrict__ b_in,
    const float* __restrict__ W_h, const float* __restrict__ b_h,
    const float* __restrict__ W_out, const float* __restrict__ b_out,
    float* __restrict__ out, int N, int H, int out_size)
{
    int t = blockIdx.x * blockDim.x + threadIdx.x;
    if (t >= H) return;

    float r  = 1.0f / (1.0f + expf(-lfo_r_logit[0]));
    float tf = (float)t;
    float amp = expf(tf * logf(r));          // r^t
    float ph  = lfo_omega[0] * tf + lfo_phi[0];
    float l0 = amp * cosf(ph);
    float l1 = amp * sinf(ph);

    float h[16];
#pragma unroll
    for (int j = 0; j < 16; j++)
        h[j] = tanhf(l0 * W_in[j] + l1 * W_in[16 + j] + b_in[j]);

    for (int lay = 0; lay < 2; lay++) {
        float hn[16];
#pragma unroll
        for (int j = 0; j < 16; j++) {
            float s = b_h[lay * 16 + j];
#pragma unroll
            for (int i = 0; i < 16; i++)
                s += h[i] * W_h[lay * 256 + i * 16 + j];
            hn[j] = tanhf(s);
        }
#pragma unroll
        for (int j = 0; j < 16; j++) h[j] = hn[j];
    }
    float s = b_out[0];
#pragma unroll
    for (int i = 0; i < 16; i++) s += h[i] * W_out[i];
    float ws = tanhf(s);

    float d  = bias[0] + depth[0] * 0.5f * (1.0f + ws);
    float td = tanf(d);
    float p  = tanhf((1.0f - td) / (1.0f + td));

    float p2 = p * p, p3 = p2 * p, p4 = p2 * p2;
    float bap[5] = { p4, -4.0f * p3, 6.0f * p2, -4.0f * p, 1.0f };
    float aap[5] = { 1.0f, -4.0f * p, 6.0f * p2, -4.0f * p3, p4 };
    float ag2 = fabsf(g2[0]);
    float den[5];
#pragma unroll
    for (int k = 0; k < 5; k++) den[k] = aap[k] - ag2 * bap[k];
    float d0 = den[0];
#pragma unroll
    for (int k = 0; k < 5; k++) {
        g_cb[t * 5 + k] = bap[k] / d0;
        g_cd[t * 5 + k] = den[k] / d0;
    }
    g_p[t] = p;
    if (N + t < out_size) out[N + t] = p;   // second output: p (H,)
}

// Fills any output tail beyond N+H (defensive; normally empty).
__global__ void tail_kernel(float* __restrict__ out, int N, int H, int out_size)
{
    float pv = g_p[H - 1];
    for (int idx = N + H + blockIdx.x * blockDim.x + threadIdx.x;
         idx < out_size; idx += gridDim.x * blockDim.x)
        out[idx] = pv;
}

// ---------------- kernel 2: fused biquad + TV-FIR + TV-LPC ----------------
// One thread per LCH-sample chunk; each thread re-runs the recurrences from
// start-WARM with zero state (transient < 1e-30 given pole radius <= ~0.73).
// Chunks whose warmup clamps to n=0 are exact.
static __device__ __forceinline__ int padj(int j) { return j + (j >> 7); }

__global__ void __launch_bounds__(TPB)
phaser_kernel(
    const float* __restrict__ x, const float* __restrict__ g1,
    const float* __restrict__ bq_dc, const float* __restrict__ bq_ff,
    const float* __restrict__ bq_fb,
    float* __restrict__ out, int N, int H, int outLim)
{
    constexpr int REG = TPB * LCH + WARM + 2;
    __shared__ float xs[REG + (REG >> 7) + 4];

    const int blockFirst  = blockIdx.x * TPB;          // first chunk id
    const int regionStart = blockFirst * LCH - WARM - 2;

    // coalesced staging of x (zeros outside [0,N))
    for (int j = threadIdx.x; j < REG; j += TPB) {
        int g = regionStart + j;
        xs[padj(j)] = (g >= 0 && g < N) ? x[g] : 0.0f;
    }
    __syncthreads();

    const int c     = blockFirst + threadIdx.x;
    const int start = c * LCH;
    if (start >= N) return;
    int nstart = start - WARM; if (nstart < 0) nstart = 0;
    int nend   = start + LCH;  if (nend > N)   nend = N;

    // biquad coefficients (stability-triangle parameterization)
    const float b0  = bq_dc[0], b1c = bq_ff[0], b2c = bq_ff[1];
    const float a1  = 2.0f * tanhf(bq_fb[0]);
    const float aa1 = fabsf(a1);
    const float a2  = ((2.0f - aa1) * tanhf(bq_fb[1]) + aa1) * 0.5f;
    const float g1v = g1[0];
    const float scaleF = (float)((double)(H - 1) / (double)(N - 1));

    // x history (from shared; zero-filled for n<0)
    int jb = nstart - regionStart;
    float x1 = xs[padj(jb - 1)];
    float x2 = xs[padj(jb - 2)];
    // h1 history (FIR taps) and LPC output history — zero state at nstart
    float f1 = 0.f, f2 = 0.f, f3 = 0.f, f4 = 0.f;
    float y1 = 0.f, y2v = 0.f, y3 = 0.f, y4 = 0.f;

    int   i0cur = -1;
    float cb0[5], cbd[5], cd0[5], cdd[5];
#pragma unroll
    for (int k = 0; k < 5; k++) { cb0[k]=cbd[k]=cd0[k]=cdd[k]=0.f; }

    for (int nn = nstart; nn < nend; ++nn) {
        int j = nn - regionStart;
        float xv = xs[padj(j)];

        // pre-filter biquad: h1[n]
        float v1   = b0 * xv + b1c * x1 + b2c * x2;
        x2 = x1; x1 = xv;
        float hcur = v1 - a1 * f1 - a2 * f2;

        // linear-interp coefficient bracketing (matches reference fp32 grid)
        float pos = (float)nn * scaleF;
        int i0 = (int)floorf(pos);
        i0 = i0 < 0 ? 0 : (i0 > H - 2 ? H - 2 : i0);
        if (i0 != i0cur) {
            i0cur = i0;
            const float* rb = g_cb + i0 * 5;
            const float* rd = g_cd + i0 * 5;
#pragma unroll
            for (int k = 0; k < 5; k++) { cb0[k] = rb[k]; cbd[k] = rb[5 + k] - rb[k]; }
#pragma unroll
            for (int k = 1; k < 5; k++) { cd0[k] = rd[k]; cdd[k] = rd[5 + k] - rd[k]; }
        }
        float frac = pos - (float)i0;

        // 5-tap time-varying FIR (hcur last -> shortest chain)
        float c0 = fmaf(frac, cbd[0], cb0[0]);
        float c1 = fmaf(frac, cbd[1], cb0[1]);
        float c2 = fmaf(frac, cbd[2], cb0[2]);
        float c3 = fmaf(frac, cbd[3], cb0[3]);
        float c4 = fmaf(frac, cbd[4], cb0[4]);
        float v = fmaf(c1, f1, fmaf(c2, f2, fmaf(c3, f3, c4 * f4)));
        v = fmaf(c0, hcur, v);

        // 4th-order time-varying LPC: y = v - d1*y1 - d2*y2 - d3*y3 - d4*y4
        float d1 = fmaf(frac, cdd[1], cd0[1]);
        float d2 = fmaf(frac, cdd[2], cd0[2]);
        float d3 = fmaf(frac, cdd[3], cd0[3]);
        float d4 = fmaf(frac, cdd[4], cd0[4]);
        float tmp = v - fmaf(d2, y2v, fmaf(d3, y3, d4 * y4));
        float yv  = fmaf(-d1, y1, tmp);

        y4 = y3; y3 = y2v; y2v = y1; y1 = yv;
        f4 = f3; f3 = f2;  f2 = f1;  f1 = hcur;

        if (nn >= start && nn < outLim)
            out[nn] = fmaf(g1v, hcur, yv);
    }
}

// ---------------- launch ----------------
extern "C" void kernel_launch(void* const* d_in, const int* in_sizes, int n_in,
                              void* d_out, int out_size)
{
    const float* x      = (const float*)d_in[0];
    const float* g1     = (const float*)d_in[1];
    const float* g2     = (const float*)d_in[2];
    const float* depth  = (const float*)d_in[3];
    const float* bias   = (const float*)d_in[4];
    const float* lfo_o  = (const float*)d_in[5];
    const float* lfo_p  = (const float*)d_in[6];
    const float* lfo_r  = (const float*)d_in[7];
    const float* W_in   = (const float*)d_in[8];
    const float* b_in   = (const float*)d_in[9];
    const float* W_h    = (const float*)d_in[10];
    const float* b_h    = (const float*)d_in[11];
    const float* W_out  = (const float*)d_in[12];
    const float* b_out  = (const float*)d_in[13];
    const float* bq_dc  = (const float*)d_in[14];
    const float* bq_ff  = (const float*)d_in[15];
    const float* bq_fb  = (const float*)d_in[16];
    float* out = (float*)d_out;

    int N = in_sizes[0];
    int H = N / HOPSZ + 1;

    int cblocks = (H + 127) / 128;
    coef_kernel<<<cblocks, 128>>>(g2, depth, bias, lfo_o, lfo_p, lfo_r,
                                  W_in, b_in, W_h, b_h, W_out, b_out,
                                  out, N, H, out_size);

    if (out_size > N + H)
        tail_kernel<<<4, 128>>>(out, N, H, out_size);

    int C = (N + LCH - 1) / LCH;
    int blocks = (C + TPB - 1) / TPB;
    int outLim = out_size < N ? out_size : N;
    phaser_kernel<<<blocks, TPB>>>(x, g1, bq_dc, bq_ff, bq_fb,
                                   out, N, H, outLim);
}

// round 2
// speedup vs baseline: 2.1943x; 2.1943x over previous
#include <cuda_runtime.h>
#include <math.h>

// ---------------- problem constants ----------------
#define HOPSZ 551
#define MAXH  2048      // H = N/551 + 1 = 1903 for N = 1<<20
#define LCH   32        // samples per chunk (one chunk per thread)
#define WARM  128       // warmup: pole radius <=0.73 -> transient ~1e-11
#define TPB   128       // chunks (threads) per block

// scratch (device globals; no allocation allowed)
__device__ float g_cb[MAXH * 5];
__device__ float g_cd[MAXH * 5];
__device__ float g_p[MAXH];

// ---------------- kernel 1: per-hop coefficients ----------------
__global__ void coef_kernel(
    const float* __restrict__ g2,
    const float* __restrict__ depth, const float* __restrict__ bias,
    const float* __restrict__ lfo_omega, const float* __restrict__ lfo_phi,
    const float* __restrict__ lfo_r_logit,
    const float* __restrict__ W_in, const float* __restrict__ b_in,
    const float* __restrict__ W_h, const float* __restrict__ b_h,
    const float* __restrict__ W_out, const float* __restrict__ b_out,
    float* __restrict__ out, int N, int H, int out_size)
{
    int t = blockIdx.x * blockDim.x + threadIdx.x;
    if (t >= H) return;

    float r  = 1.0f / (1.0f + expf(-lfo_r_logit[0]));
    float tf = (float)t;
    float amp = expf(tf * logf(r));          // r^t
    float ph  = lfo_omega[0] * tf + lfo_phi[0];
    float l0 = amp * cosf(ph);
    float l1 = amp * sinf(ph);

    float h[16];
#pragma unroll
    for (int j = 0; j < 16; j++)
        h[j] = tanhf(l0 * W_in[j] + l1 * W_in[16 + j] + b_in[j]);

    for (int lay = 0; lay < 2; lay++) {
        float hn[16];
#pragma unroll
        for (int j = 0; j < 16; j++) {
            float s = b_h[lay * 16 + j];
#pragma unroll
            for (int i = 0; i < 16; i++)
                s += h[i] * W_h[lay * 256 + i * 16 + j];
            hn[j] = tanhf(s);
        }
#pragma unroll
        for (int j = 0; j < 16; j++) h[j] = hn[j];
    }
    float s = b_out[0];
#pragma unroll
    for (int i = 0; i < 16; i++) s += h[i] * W_out[i];
    float ws = tanhf(s);

    float d  = bias[0] + depth[0] * 0.5f * (1.0f + ws);
    float td = tanf(d);
    float p  = tanhf((1.0f - td) / (1.0f + td));

    float p2 = p * p, p3 = p2 * p, p4 = p2 * p2;
    float bap[5] = { p4, -4.0f * p3, 6.0f * p2, -4.0f * p, 1.0f };
    float aap[5] = { 1.0f, -4.0f * p, 6.0f * p2, -4.0f * p3, p4 };
    float ag2 = fabsf(g2[0]);
    float den[5];
#pragma unroll
    for (int k = 0; k < 5; k++) den[k] = aap[k] - ag2 * bap[k];
    float d0 = den[0];
#pragma unroll
    for (int k = 0; k < 5; k++) {
        g_cb[t * 5 + k] = bap[k] / d0;
        g_cd[t * 5 + k] = den[k] / d0;
    }
    g_p[t] = p;
    if (N + t < out_size) out[N + t] = p;   // second output: p (H,)
}

// Fills any output tail beyond N+H (defensive; normally empty).
__global__ void tail_kernel(float* __restrict__ out, int N, int H, int out_size)
{
    float pv = g_p[H - 1];
    for (int idx = N + H + blockIdx.x * blockDim.x + threadIdx.x;
         idx < out_size; idx += gridDim.x * blockDim.x)
        out[idx] = pv;
}

// ---------------- kernel 2: fused biquad + TV-FIR + TV-LPC ----------------
// One thread per LCH-sample chunk; re-runs recurrences from start-WARM with
// zero state. Lanes are LCH=32 floats apart -> pad shared every 32 words.
static __device__ __forceinline__ int padj(int j) { return j + (j >> 5); }

__global__ void __launch_bounds__(TPB)
phaser_kernel(
    const float* __restrict__ x, const float* __restrict__ g1,
    const float* __restrict__ bq_dc, const float* __restrict__ bq_ff,
    const float* __restrict__ bq_fb,
    float* __restrict__ out, int N, int H, int outLim)
{
    constexpr int REG = TPB * LCH + WARM + 2;
    __shared__ float xs[REG + (REG >> 5) + 4];

    const int blockFirst  = blockIdx.x * TPB;          // first chunk id
    const int regionStart = blockFirst * LCH - WARM - 2;

    // coalesced staging of x (zeros outside [0,N))
    for (int j = threadIdx.x; j < REG; j += TPB) {
        int g = regionStart + j;
        xs[padj(j)] = (g >= 0 && g < N) ? x[g] : 0.0f;
    }
    __syncthreads();

    const int c     = blockFirst + threadIdx.x;
    const int start = c * LCH;
    if (start >= N) return;
    int nstart = start - WARM; if (nstart < 0) nstart = 0;
    int nend   = start + LCH;  if (nend > N)   nend = N;

    // biquad coefficients (stability-triangle parameterization)
    const float b0  = bq_dc[0], b1c = bq_ff[0], b2c = bq_ff[1];
    const float a1  = 2.0f * tanhf(bq_fb[0]);
    const float aa1 = fabsf(a1);
    const float a2  = ((2.0f - aa1) * tanhf(bq_fb[1]) + aa1) * 0.5f;
    const float g1v = g1[0];
    const float scaleF = (float)((double)(H - 1) / (double)(N - 1));

    // x history (from shared; region includes 2 lead-in samples)
    int jb = nstart - regionStart;
    float x1 = xs[padj(jb - 1)];
    float x2 = xs[padj(jb - 2)];
    // filter state (zero at nstart)
    float f1 = 0.f, f2 = 0.f, f3 = 0.f, f4 = 0.f;
    float y1 = 0.f, y2v = 0.f, y3 = 0.f, y4 = 0.f;

    int   i0cur = -1;
    float cb0[5], cbd[5], cd0[5], cdd[5];
#pragma unroll
    for (int k = 0; k < 5; k++) { cb0[k]=cbd[k]=cd0[k]=cdd[k]=0.f; }

#define PH_STEP(NN, DO_STORE)                                                 \
    {                                                                         \
        float xv = xs[padj((NN) - regionStart)];                              \
        float v1   = b0 * xv + b1c * x1 + b2c * x2;                           \
        x2 = x1; x1 = xv;                                                     \
        float hcur = v1 - a1 * f1 - a2 * f2;                                  \
        float pos = (float)(NN) * scaleF;                                     \
        int i0 = (int)floorf(pos);                                            \
        i0 = i0 < 0 ? 0 : (i0 > H - 2 ? H - 2 : i0);                          \
        if (i0 != i0cur) {                                                    \
            i0cur = i0;                                                       \
            const float* rb = g_cb + i0 * 5;                                  \
            const float* rd = g_cd + i0 * 5;                                  \
            _Pragma("unroll")                                                 \
            for (int k = 0; k < 5; k++) { cb0[k] = rb[k]; cbd[k] = rb[5+k]-rb[k]; } \
            _Pragma("unroll")                                                 \
            for (int k = 1; k < 5; k++) { cd0[k] = rd[k]; cdd[k] = rd[5+k]-rd[k]; } \
        }                                                                     \
        float frac = pos - (float)i0;                                         \
        float c0 = fmaf(frac, cbd[0], cb0[0]);                                \
        float c1 = fmaf(frac, cbd[1], cb0[1]);                                \
        float c2 = fmaf(frac, cbd[2], cb0[2]);                                \
        float c3 = fmaf(frac, cbd[3], cb0[3]);                                \
        float c4 = fmaf(frac, cbd[4], cb0[4]);                                \
        float v = fmaf(c1, f1, fmaf(c2, f2, fmaf(c3, f3, c4 * f4)));          \
        v = fmaf(c0, hcur, v);                                                \
        float d1 = fmaf(frac, cdd[1], cd0[1]);                                \
        float d2 = fmaf(frac, cdd[2], cd0[2]);                                \
        float d3 = fmaf(frac, cdd[3], cd0[3]);                                \
        float d4 = fmaf(frac, cdd[4], cd0[4]);                                \
        float tmp = v - fmaf(d2, y2v, fmaf(d3, y3, d4 * y4));                 \
        float yv  = fmaf(-d1, y1, tmp);                                       \
        y4 = y3; y3 = y2v; y2v = y1; y1 = yv;                                 \
        f4 = f3; f3 = f2;  f2 = f1;  f1 = hcur;                               \
        if (DO_STORE && (NN) < outLim)                                        \
            out[(NN)] = fmaf(g1v, hcur, yv);                                  \
    }

    // warmup (no stores)
#pragma unroll 4
    for (int nn = nstart; nn < start; ++nn) PH_STEP(nn, 0)
    // payload (stores)
#pragma unroll 4
    for (int nn = start; nn < nend; ++nn) PH_STEP(nn, 1)
#undef PH_STEP
}

// ---------------- launch ----------------
extern "C" void kernel_launch(void* const* d_in, const int* in_sizes, int n_in,
                              void* d_out, int out_size)
{
    const float* x      = (const float*)d_in[0];
    const float* g1     = (const float*)d_in[1];
    const float* g2     = (const float*)d_in[2];
    const float* depth  = (const float*)d_in[3];
    const float* bias   = (const float*)d_in[4];
    const float* lfo_o  = (const float*)d_in[5];
    const float* lfo_p  = (const float*)d_in[6];
    const float* lfo_r  = (const float*)d_in[7];
    const float* W_in   = (const float*)d_in[8];
    const float* b_in   = (const float*)d_in[9];
    const float* W_h    = (const float*)d_in[10];
    const float* b_h    = (const float*)d_in[11];
    const float* W_out  = (const float*)d_in[12];
    const float* b_out  = (const float*)d_in[13];
    const float* bq_dc  = (const float*)d_in[14];
    const float* bq_ff  = (const float*)d_in[15];
    const float* bq_fb  = (const float*)d_in[16];
    float* out = (float*)d_out;

    int N = in_sizes[0];
    int H = N / HOPSZ + 1;

    int cblocks = (H + 127) / 128;
    coef_kernel<<<cblocks, 128>>>(g2, depth, bias, lfo_o, lfo_p, lfo_r,
                                  W_in, b_in, W_h, b_h, W_out, b_out,
                                  out, N, H, out_size);

    if (out_size > N + H)
        tail_kernel<<<4, 128>>>(out, N, H, out_size);

    int C = (N + LCH - 1) / LCH;
    int blocks = (C + TPB - 1) / TPB;
    int outLim = out_size < N ? out_size : N;
    phaser_kernel<<<blocks, TPB>>>(x, g1, bq_dc, bq_ff, bq_fb,
                                   out, N, H, outLim);
}